// round 13
// baseline (speedup 1.0000x reference)
#include <cuda_runtime.h>
#include <cuda_bf16.h>
#include <cstdint>

// NEAT DAG — R12: bf16 hi/lo 3-pass HMMA + split-K across 2 warp groups.
// x[4096,512] f32, W[1536,2048] f32 lower-tri, b[1536], out[4096,256].
// 128 CTAs x 32 batch rows, 512 threads (16 warps):
//   group 0 (warps 0-7) computes even 64-K blocks, group 1 odd blocks.
//   4 SMEM tile buffers (2 groups x double-buffered), reg-prefetched,
//   one barrier per iteration (2 blocks retired per barrier).

#define NTH 512
#define BR 32
#define NIN 512
#define NN 2048
#define NCHUNK 24
#define ZST 66

__device__ __align__(256) __nv_bfloat16 g_Ahi[4096u * 2048u];
__device__ __align__(256) __nv_bfloat16 g_Alo[4096u * 2048u];
__device__ __align__(256) __nv_bfloat16 g_Whi[1536u * 2048u];
__device__ __align__(256) __nv_bfloat16 g_Wlo[1536u * 2048u];

// ---- smem layout (bytes) ----
#define OFF_BIAS 0
#define OFF_OS   256                   // 32*9*4
#define OFF_ZSM  1536                  // 32*66*4
#define OFF_WD   9984                  // 64*68*4
#define OFF_BUFS 28672                 // 4 buffers follow
#define BUFSZ    24576                 // AHI 4K | ALO 4K | WHI 8K | WLO 8K
#define SMEM_SZ  (OFF_BUFS + 4 * BUFSZ)  // 126976
#define AHI 0
#define ALO 4096
#define WHI 8192
#define WLO 16384

#define SW128(b) ((b) ^ (((b) >> 3) & 0x70))

__device__ __forceinline__ uint32_t smem_u32(const void* p) {
    uint32_t a;
    asm("{ .reg .u64 t; cvta.to.shared.u64 t, %1; cvt.u32.u64 %0, t; }" : "=r"(a) : "l"(p));
    return a;
}
__device__ __forceinline__ void ldm4(uint32_t* r, uint32_t addr) {
    asm volatile("ldmatrix.sync.aligned.m8n8.x4.shared.b16 {%0,%1,%2,%3}, [%4];"
                 : "=r"(r[0]), "=r"(r[1]), "=r"(r[2]), "=r"(r[3]) : "r"(addr));
}
__device__ __forceinline__ void mma_bf16(float* d, const uint32_t* a,
                                         uint32_t b0, uint32_t b1) {
    asm volatile(
        "mma.sync.aligned.m16n8k16.row.col.f32.bf16.bf16.f32 "
        "{%0,%1,%2,%3}, {%4,%5,%6,%7}, {%8,%9}, {%0,%1,%2,%3};"
        : "+f"(d[0]), "+f"(d[1]), "+f"(d[2]), "+f"(d[3])
        : "r"(a[0]), "r"(a[1]), "r"(a[2]), "r"(a[3]), "r"(b0), "r"(b1));
}
__device__ __forceinline__ void split4(float4 v, __nv_bfloat16* h, __nv_bfloat16* l) {
    float f[4] = {v.x, v.y, v.z, v.w};
    #pragma unroll
    for (int j = 0; j < 4; j++) {
        h[j] = __float2bfloat16(f[j]);
        l[j] = __float2bfloat16(f[j] - __bfloat162float(h[j]));
    }
}

#define XN4 (4096 * 512 / 4)
#define WN4 (1536 * 2048 / 4)
__global__ void conv_kernel(const float* __restrict__ x, const float* __restrict__ W) {
    int idx = blockIdx.x * blockDim.x + threadIdx.x;
    __align__(8) __nv_bfloat16 h[4], l[4];
    if (idx < XN4) {
        int r = idx >> 7, c = (idx & 127) * 4;
        split4(*(const float4*)&x[(size_t)r * NIN + c], h, l);
        size_t o = (size_t)r * NN + c;
        *(uint2*)&g_Ahi[o] = *(uint2*)h;
        *(uint2*)&g_Alo[o] = *(uint2*)l;
    } else if (idx < XN4 + WN4) {
        int j = idx - XN4;
        int r = j >> 9, c = (j & 511) * 4;
        size_t o = (size_t)r * NN + c;
        split4(*(const float4*)&W[o], h, l);
        *(uint2*)&g_Whi[o] = *(uint2*)h;
        *(uint2*)&g_Wlo[o] = *(uint2*)l;
    }
}

__global__ void __launch_bounds__(NTH, 1)
neat_mma_kernel(const float* __restrict__ W,
                const float* __restrict__ bias,
                float* __restrict__ out)
{
    extern __shared__ char sm[];
    const uint32_t sb = smem_u32(sm);
    const int tid = threadIdx.x;
    const int lane = tid & 31, wrp = tid >> 5;
    const int grp = wrp >> 3, w8 = wrp & 7;
    const int row0 = blockIdx.x * BR;

    float* biasS = (float*)(sm + OFF_BIAS);
    float* oS    = (float*)(sm + OFF_OS);     // [32][9]
    float* zSm   = (float*)(sm + OFF_ZSM);    // [32][66]
    float* Wd    = (float*)(sm + OFF_WD);     // [64][68] fp32 diag

    // mma mapping within the 32x64 Z tile (per group)
    const int rt16 = (w8 & 1) * 16;
    const int c0   = (w8 >> 1) * 16;
    const int mrow = lane & 7, mid = lane >> 3;
    const int aRowB = (rt16 + mrow + ((mid & 1) << 3)) * 128 + ((mid >> 1) << 4);
    const int wRowB = (c0 + mrow + ((mid >> 1) << 3)) * 128 + ((mid & 1) << 4);

    // staging: half h stages block 2*it+h; 256 threads per half
    const int h  = tid >> 8;
    const int st = tid & 255;
    const int sr = st >> 3, sg = st & 7;
    const uint32_t soA  = SW128((uint32_t)(sr * 128 + sg * 16));
    const uint32_t soW1 = SW128((uint32_t)((sr + 32) * 128 + sg * 16));

    // initial prefetch: chunk 0, block h (kb = 64*h)
    uint4 pAh, pAl, pW0h, pW0l, pW1h, pW1l;
    {
        int kb = 64 * h;
        size_t ga = (size_t)(row0 + sr) * NN + kb + 8 * sg;
        pAh = *(const uint4*)&g_Ahi[ga];
        pAl = *(const uint4*)&g_Alo[ga];
        size_t g0w = (size_t)sr * NN + kb + 8 * sg;
        size_t g1w = (size_t)(sr + 32) * NN + kb + 8 * sg;
        pW0h = *(const uint4*)&g_Whi[g0w];
        pW0l = *(const uint4*)&g_Wlo[g0w];
        pW1h = *(const uint4*)&g_Whi[g1w];
        pW1l = *(const uint4*)&g_Wlo[g1w];
    }
    int git = 0;   // global iteration counter -> buffer parity

    for (int ch = 0; ch < NCHUNK; ch++) {
        const int i0 = ch * 64, g0 = NIN + i0;
        const int nblk = g0 >> 6;
        const int nit = (nblk + 1) >> 1;
        float d0[4] = {0.f, 0.f, 0.f, 0.f}, d1[4] = {0.f, 0.f, 0.f, 0.f};

        for (int it = 0; it < nit; it++) {
            const int par = git & 1;
            // commit prefetched tiles -> buffer (h, par)
            {
                char* bp = sm + OFF_BUFS + ((h << 1) | par) * BUFSZ;
                *(uint4*)(bp + AHI + soA)  = pAh;
                *(uint4*)(bp + ALO + soA)  = pAl;
                *(uint4*)(bp + WHI + soA)  = pW0h;
                *(uint4*)(bp + WLO + soA)  = pW0l;
                *(uint4*)(bp + WHI + soW1) = pW1h;
                *(uint4*)(bp + WLO + soW1) = pW1l;
            }
            __syncthreads();
            // prefetch next block for this half
            {
                int nb = 2 * (it + 1) + h, nch = ch, ni0 = i0;
                if (nb >= nblk) { nch = ch + 1; ni0 = nch * 64; nb = h; }
                if (nch < NCHUNK) {
                    int nkb = nb * 64;
                    size_t ga = (size_t)(row0 + sr) * NN + nkb + 8 * sg;
                    pAh = *(const uint4*)&g_Ahi[ga];
                    pAl = *(const uint4*)&g_Alo[ga];
                    size_t g0w = (size_t)(ni0 + sr) * NN + nkb + 8 * sg;
                    size_t g1w = (size_t)(ni0 + sr + 32) * NN + nkb + 8 * sg;
                    pW0h = *(const uint4*)&g_Whi[g0w];
                    pW0l = *(const uint4*)&g_Wlo[g0w];
                    pW1h = *(const uint4*)&g_Whi[g1w];
                    pW1l = *(const uint4*)&g_Wlo[g1w];
                }
            }
            // compute: group grp handles block 2*it+grp (if it exists)
            if (2 * it + grp < nblk) {
                const uint32_t bb = sb + OFF_BUFS + ((grp << 1) | par) * BUFSZ;
                #pragma unroll
                for (int ks = 0; ks < 4; ks++) {
                    uint32_t ao = (uint32_t)(aRowB + 32 * ks);
                    uint32_t wo = (uint32_t)(wRowB + 32 * ks);
                    uint32_t ah[4], al[4], wh[4], wl[4];
                    ldm4(ah, bb + AHI + SW128(ao));
                    ldm4(al, bb + ALO + SW128(ao));
                    ldm4(wh, bb + WHI + SW128(wo));
                    ldm4(wl, bb + WLO + SW128(wo));
                    mma_bf16(d0, ah, wh[0], wh[1]);
                    mma_bf16(d0, ah, wl[0], wl[1]);
                    mma_bf16(d0, al, wh[0], wh[1]);
                    mma_bf16(d1, ah, wh[2], wh[3]);
                    mma_bf16(d1, ah, wl[2], wl[3]);
                    mma_bf16(d1, al, wh[2], wh[3]);
                }
            }
            git++;
        }

        // ---- stage fp32 diagonal block + bias ----
        #pragma unroll
        for (int i = 0; i < 2; i++) {
            int idx = tid + i * NTH;            // 0..1023
            int r = idx >> 4, q = idx & 15;
            *(float4*)&Wd[r * 68 + 4 * q] =
                *(const float4*)&W[(size_t)(i0 + r) * NN + g0 + 4 * q];
        }
        if (tid < 64) biasS[tid] = bias[i0 + tid];
        __syncthreads();

        // ---- merge group fragments into zSm ----
        {
            int rw = rt16 + (lane >> 2);
            int cb = c0 + 2 * (lane & 3);
            if (grp == 0) {
                *(float2*)&zSm[rw * ZST + cb] =
                    make_float2(d0[0] + biasS[cb], d0[1] + biasS[cb + 1]);
                *(float2*)&zSm[(rw + 8) * ZST + cb] =
                    make_float2(d0[2] + biasS[cb], d0[3] + biasS[cb + 1]);
                *(float2*)&zSm[rw * ZST + cb + 8] =
                    make_float2(d1[0] + biasS[cb + 8], d1[1] + biasS[cb + 9]);
                *(float2*)&zSm[(rw + 8) * ZST + cb + 8] =
                    make_float2(d1[2] + biasS[cb + 8], d1[3] + biasS[cb + 9]);
            }
            __syncthreads();
            if (grp == 1) {
                float2 t;
                t = *(float2*)&zSm[rw * ZST + cb];
                t.x += d0[0]; t.y += d0[1];
                *(float2*)&zSm[rw * ZST + cb] = t;
                t = *(float2*)&zSm[(rw + 8) * ZST + cb];
                t.x += d0[2]; t.y += d0[3];
                *(float2*)&zSm[(rw + 8) * ZST + cb] = t;
                t = *(float2*)&zSm[rw * ZST + cb + 8];
                t.x += d1[0]; t.y += d1[1];
                *(float2*)&zSm[rw * ZST + cb + 8] = t;
                t = *(float2*)&zSm[(rw + 8) * ZST + cb + 8];
                t.x += d1[2]; t.y += d1[3];
                *(float2*)&zSm[(rw + 8) * ZST + cb + 8] = t;
            }
        }
        __syncthreads();

        // ---- triangle: 8 sub-blocks of 8 nodes ----
        for (int s = 0; s < 8; s++) {
            if (tid < 32) {
                int row = tid;
                float zl[8], ov[8];
                #pragma unroll
                for (int j = 0; j < 8; j++) zl[j] = zSm[row * ZST + 8 * s + j];
                #pragma unroll
                for (int j = 0; j < 8; j++) {
                    float t5 = fminf(fmaxf(5.0f * zl[j], -60.0f), 60.0f);
                    float o  = __fdividef(1.0f, 1.0f + __expf(-t5));
                    ov[j] = o;
                    #pragma unroll
                    for (int k = j + 1; k < 8; k++)
                        zl[k] = fmaf(Wd[(8 * s + k) * 68 + (8 * s + j)], o, zl[k]);
                }
                #pragma unroll
                for (int j = 0; j < 8; j++) oS[row * 9 + j] = ov[j];
                __align__(16) __nv_bfloat16 hh[8], ll[8];
                #pragma unroll
                for (int j = 0; j < 8; j++) {
                    hh[j] = __float2bfloat16(ov[j]);
                    ll[j] = __float2bfloat16(ov[j] - __bfloat162float(hh[j]));
                }
                size_t go = (size_t)(row0 + row) * NN + g0 + 8 * s;
                *(uint4*)&g_Ahi[go] = *(uint4*)hh;
                *(uint4*)&g_Alo[go] = *(uint4*)ll;
                int col0 = g0 + 8 * s;
                if (col0 >= NN - 256) {
                    int oc = col0 - (NN - 256);
                    #pragma unroll
                    for (int j = 0; j < 8; j++)
                        out[(size_t)(row0 + row) * 256 + oc + j] = ov[j];
                }
            }
            __syncthreads();
            if (s < 7) {
                int row = lane;
                float ov[8];
                #pragma unroll
                for (int j = 0; j < 8; j++) ov[j] = oS[row * 9 + j];
                for (int k = 8 * (s + 1) + wrp; k < 64; k += 16) {
                    float z = zSm[row * ZST + k];
                    #pragma unroll
                    for (int j = 0; j < 8; j++)
                        z = fmaf(ov[j], Wd[k * 68 + (8 * s + j)], z);
                    zSm[row * ZST + k] = z;
                }
                __syncthreads();
            }
        }
        __syncthreads();
    }
}

extern "C" void kernel_launch(void* const* d_in, const int* in_sizes, int n_in,
                              void* d_out, int out_size) {
    const float* x    = (const float*)d_in[0];
    const float* W    = (const float*)d_in[1];
    const float* bias = (const float*)d_in[2];
    float* out        = (float*)d_out;
    (void)in_sizes; (void)n_in; (void)out_size;

    conv_kernel<<<(XN4 + WN4 + NTH - 1) / NTH, NTH>>>(x, W);
    cudaFuncSetAttribute(neat_mma_kernel,
                         cudaFuncAttributeMaxDynamicSharedMemorySize, SMEM_SZ);
    neat_mma_kernel<<<4096 / BR, NTH, SMEM_SZ>>>(W, bias, out);
}